// round 16
// baseline (speedup 1.0000x reference)
#include <cuda_runtime.h>
#include <cstdint>

#define HH 80
#define WW 96
#define TTT 112
#define NS (HH*WW*TTT)
#define NC 16
#define NCC 59
#define FH 40
#define FW 48
#define FT 56
#define PH 84
#define PW 100
#define PT 116
#define NSP (PH*PW*PT)

// ---------------------------------------------------------------------------
// scratch: packed activations = (bf16_hi << 16) | bf16_lo
// ---------------------------------------------------------------------------
__device__ uint32_t g_sp_stack[NCC*NS];
__device__ float    g_xw[NC*NS];
__device__ float    g_pm[NC*NS];
__device__ float    g_pf[NC*NSP];
__device__ uint32_t g_sp_t1[NCC*NS];
__device__ float    g_h[NC*NS];
__device__ uint32_t g_sp_h[NC*NS];
__device__ uint32_t g_sp_t2[NC*NS];
__device__ uint32_t g_sp_hr[NC*NS];

// B tables: [iter = tap*NCH+chunk][ks3][nt][lane32], uint4 = (b0h,b1h,b0l,b1l)
__device__ uint4 g_Bf1a[36*3*8*32];
__device__ uint4 g_Bf1b[36*3*2*32];
__device__ uint4 g_Bf2a[9*3*2*32];
__device__ uint4 g_Bf2b[9*3*2*32];
__device__ uint4 g_Bff [9*3*1*32];

// ---------------------------------------------------------------------------
// helpers
// ---------------------------------------------------------------------------
__device__ __forceinline__ uint32_t smem_u32(const void* p) {
    uint32_t a;
    asm("{ .reg .u64 t; cvta.to.shared.u64 t, %1; cvt.u32.u64 %0, t; }" : "=r"(a) : "l"(p));
    return a;
}
__device__ __forceinline__ uint32_t prmt(uint32_t a, uint32_t b, uint32_t s) {
    uint32_t d;
    asm("prmt.b32 %0, %1, %2, %3;" : "=r"(d) : "r"(a), "r"(b), "r"(s));
    return d;
}
__device__ __forceinline__ uint32_t split_pack(float v) {
    uint32_t u = __float_as_uint(v);
    uint32_t hb = u & 0xffff0000u;
    float r = v - __uint_as_float(hb);
    uint16_t lo;
    asm("cvt.rn.bf16.f32 %0, %1;" : "=h"(lo) : "f"(r));
    return hb | (uint32_t)lo;
}
__device__ __forceinline__ void split_pair(float v0, float v1, uint32_t& hi, uint32_t& lo) {
    uint32_t u0 = __float_as_uint(v0), u1 = __float_as_uint(v1);
    hi = prmt(u0, u1, 0x7632);
    float h0 = __uint_as_float(u0 & 0xffff0000u);
    float h1 = __uint_as_float(u1 & 0xffff0000u);
    float l0 = v0 - h0, l1 = v1 - h1;
    asm("cvt.rn.satfinite.bf16x2.f32 %0, %1, %2;" : "=r"(lo) : "f"(l1), "f"(l0));
}
__device__ __forceinline__ void mma_bf16(float* c, const uint32_t* a, uint32_t b0, uint32_t b1) {
    asm volatile("mma.sync.aligned.m16n8k16.row.col.f32.bf16.bf16.f32 "
        "{%0,%1,%2,%3}, {%4,%5,%6,%7}, {%8,%9}, {%0,%1,%2,%3};"
        : "+f"(c[0]), "+f"(c[1]), "+f"(c[2]), "+f"(c[3])
        : "r"(a[0]), "r"(a[1]), "r"(a[2]), "r"(a[3]), "r"(b0), "r"(b1));
}
// 16B cp.async, L1-allocating (.ca — R11 proved .cg's L1 bypass regresses)
__device__ __forceinline__ void cpasync16(uint32_t dst, const void* src, bool ok) {
    int sz = ok ? 16 : 0;
    asm volatile("cp.async.ca.shared.global [%0], [%1], 16, %2;"
                 :: "r"(dst), "l"(src), "r"(sz) : "memory");
}
#define CP_COMMIT() asm volatile("cp.async.commit_group;" ::: "memory")
#define CP_WAIT0()  asm volatile("cp.async.wait_group 0;" ::: "memory")
#define CP_WAIT1()  asm volatile("cp.async.wait_group 1;" ::: "memory")

// ---------------------------------------------------------------------------
// repack (R5-proven layout)
// ---------------------------------------------------------------------------
__device__ void repack_one(int idx, const float* __restrict__ w, uint4* __restrict__ dst,
                           int NT, int NCH, int CIN, int COUT)
{
    int lane = idx & 31;
    int rest = idx >> 5;
    int nt = rest % NT;   rest /= NT;
    int ks = rest % 3;    rest /= 3;
    int iter = rest;
    int tap = iter / NCH, chunk = iter % NCH;
    int n = nt*8 + (lane >> 2);
    int q = lane & 3;
    int dh = tap/3, dw = tap%3;
    float v[4];
    #pragma unroll
    for (int j = 0; j < 4; j++) {
        int k = ks*16 + q*2 + (j >> 1)*8 + (j & 1);
        int cil = k/3, dt = k - 3*cil;
        int ci = chunk*16 + cil;
        v[j] = (ci < CIN && n < COUT) ? w[(n*CIN + ci)*27 + dh*9 + dw*3 + dt] : 0.0f;
    }
    uint32_t h0, l0, h1, l1;
    split_pair(v[0], v[1], h0, l0);
    split_pair(v[2], v[3], h1, l1);
    dst[idx] = make_uint4(h0, h1, l0, l1);
}

// ---------------------------------------------------------------------------
// prep = repack + warp/upsample (R9-proven)
// ---------------------------------------------------------------------------
#define RPB 152
__global__ void prep_kernel(const float* __restrict__ x, const float* __restrict__ y,
                            const float* __restrict__ flow,
                            const float* __restrict__ w1a, const float* __restrict__ w1b,
                            const float* __restrict__ w2a, const float* __restrict__ w2b,
                            const float* __restrict__ wf)
{
    if (blockIdx.x < RPB) {
        int gi = blockIdx.x*256 + threadIdx.x;
        if      (gi < 27648)  repack_one(gi,        w1a, g_Bf1a, 8, 4, 59, 59);
        else if (gi < 34560)  repack_one(gi-27648,  w1b, g_Bf1b, 2, 4, 59, 16);
        else if (gi < 36288)  repack_one(gi-34560,  w2a, g_Bf2a, 2, 1, 16, 16);
        else if (gi < 38016)  repack_one(gi-36288,  w2b, g_Bf2b, 2, 1, 16, 16);
        else if (gi < 38880)  repack_one(gi-38016,  wf,  g_Bff,  1, 1, 16, 3);
        return;
    }
    int idx = (blockIdx.x - RPB)*256 + threadIdx.x;
    if (idx >= NS) return;
    int t = idx % TTT, w = (idx / TTT) % WW, h = idx / (TTT*WW);

    float ph = h * (39.0f/79.0f), pw = w * (47.0f/95.0f), pt = t * (55.0f/111.0f);
    int ih = (int)ph; if (ih > FH-2) ih = FH-2;
    int iw = (int)pw; if (iw > FW-2) iw = FW-2;
    int it = (int)pt; if (it > FT-2) it = FT-2;
    float fh = ph - (float)ih, fw = pw - (float)iw, ft = pt - (float)it;

    float fu[3];
    #pragma unroll
    for (int c = 0; c < 3; c++) {
        const float* fc = flow + c*(FH*FW*FT) + (ih*FW + iw)*FT + it;
        float v000 = fc[0],        v001 = fc[1];
        float v010 = fc[FT],       v011 = fc[FT+1];
        float v100 = fc[FW*FT],    v101 = fc[FW*FT+1];
        float v110 = fc[FW*FT+FT], v111 = fc[FW*FT+FT+1];
        float a0 = v000*(1.0f-ft) + v001*ft;
        float a1 = v010*(1.0f-ft) + v011*ft;
        float a2 = v100*(1.0f-ft) + v101*ft;
        float a3 = v110*(1.0f-ft) + v111*ft;
        float b0 = a0*(1.0f-fw) + a1*fw;
        float b1 = a2*(1.0f-fw) + a3*fw;
        fu[c] = 2.0f*(b0*(1.0f-fh) + b1*fh);
    }

    float cx = (float)h + fu[0], cy = (float)w + fu[1], cz = (float)t + fu[2];
    float x0f = floorf(cx), y0f = floorf(cy), z0f = floorf(cz);
    float fx = cx - x0f, fy = cy - y0f, fz = cz - z0f;
    int x0 = (int)x0f, y0 = (int)y0f, z0 = (int)z0f;

    float acc[NC];
    #pragma unroll
    for (int c = 0; c < NC; c++) acc[c] = 0.0f;
    #pragma unroll
    for (int dx = 0; dx < 2; dx++)
    #pragma unroll
    for (int dy = 0; dy < 2; dy++)
    #pragma unroll
    for (int dz = 0; dz < 2; dz++) {
        int ix = x0+dx, iy = y0+dy, iz = z0+dz;
        if (ix < 0 || ix >= HH || iy < 0 || iy >= WW || iz < 0 || iz >= TTT) continue;
        float wgt = (dx ? fx : 1.0f-fx) * (dy ? fy : 1.0f-fy) * (dz ? fz : 1.0f-fz);
        const float* xp = x + (ix*WW + iy)*TTT + iz;
        #pragma unroll
        for (int c = 0; c < NC; c++) acc[c] += wgt * xp[c*NS];
    }
    #pragma unroll
    for (int c = 0; c < NC; c++) {
        g_xw[c*NS + idx] = acc[c];
        g_sp_stack[c*NS + idx]      = split_pack(acc[c]);
        g_sp_stack[(43+c)*NS + idx] = split_pack(y[c*NS + idx]);
    }
}

// ---------------------------------------------------------------------------
// box (R7-proven)
// ---------------------------------------------------------------------------
__global__ void box_kernel(const float* __restrict__ y)
{
    int c = blockIdx.y;
    if (blockIdx.x < 840) {
        int id = blockIdx.x*256 + threadIdx.x;
        int t4 = (id % 28)*4;
        int w  = (id / 28) % WW;
        int h  = id / (28*WW);
        float R[6];
        #pragma unroll
        for (int e = 0; e < 6; e++) R[e] = 0.0f;
        #pragma unroll
        for (int dh = -1; dh <= 1; dh++) {
            int gh = h + dh; if ((unsigned)gh >= HH) continue;
            #pragma unroll
            for (int dw = -1; dw <= 1; dw++) {
                int gw = w + dw; if ((unsigned)gw >= WW) continue;
                const float* row = g_xw + c*NS + (gh*WW + gw)*TTT;
                #pragma unroll
                for (int e = 0; e < 6; e++) {
                    int gt = t4 - 1 + e;
                    if ((unsigned)gt < TTT) R[e] += row[gt];
                }
            }
        }
        float* o = g_pm + c*NS + (h*WW + w)*TTT + t4;
        #pragma unroll
        for (int i = 0; i < 4; i++) o[i] = R[i] + R[i+1] + R[i+2];
    } else {
        int id = (blockIdx.x - 840)*256 + threadIdx.x;
        if (id >= 243600) return;
        int t4 = (id % 29)*4;
        int b  = (id / 29) % PW;
        int a  = id / (29*PW);
        int hc = a - 2, wc = b - 2;
        float R[6];
        #pragma unroll
        for (int e = 0; e < 6; e++) R[e] = 0.0f;
        #pragma unroll
        for (int dh = -1; dh <= 1; dh++) {
            int gh = hc + dh; if ((unsigned)gh >= HH) continue;
            #pragma unroll
            for (int dw = -1; dw <= 1; dw++) {
                int gw = wc + dw; if ((unsigned)gw >= WW) continue;
                const float* row = y + c*NS + (gh*WW + gw)*TTT;
                #pragma unroll
                for (int e = 0; e < 6; e++) {
                    int gt = t4 - 3 + e;
                    if ((unsigned)gt < TTT) R[e] += row[gt];
                }
            }
        }
        float* o = g_pf + c*NSP + (a*PW + b)*PT + t4;
        #pragma unroll
        for (int i = 0; i < 4; i++) o[i] = R[i] + R[i+1] + R[i+2];
    }
}

// ---------------------------------------------------------------------------
// corr (R13: 4 voxels/thread, float4; bit-identical results)
// ---------------------------------------------------------------------------
__global__ void __launch_bounds__(256)
corr_kernel()
{
    int id = blockIdx.x*256 + threadIdx.x;              // NS/4 = 215040 exact
    int t4 = (id % 28)*4;
    int w  = (id / 28) % WW;
    int h  = id / (28*WW);
    int vox = (h*WW + w)*TTT + t4;

    float4 pm4[NC];
    #pragma unroll
    for (int c = 0; c < NC; c++)
        pm4[c] = *(const float4*)(g_pm + c*NS + vox);

    #pragma unroll
    for (int i = 0; i < 3; i++)
    #pragma unroll
    for (int j = 0; j < 3; j++) {
        const float* rowbase = g_pf + ((h + 2*i)*PW + (w + 2*j))*PT + t4;
        float acc[3][4];
        #pragma unroll
        for (int k = 0; k < 3; k++)
            #pragma unroll
            for (int e = 0; e < 4; e++) acc[k][e] = 0.0f;

        #pragma unroll
        for (int c = 0; c < NC; c++) {
            float4 f0 = *(const float4*)(rowbase + c*NSP);
            float4 f1 = *(const float4*)(rowbase + c*NSP + 4);
            float f[8] = {f0.x, f0.y, f0.z, f0.w, f1.x, f1.y, f1.z, f1.w};
            const float* pmc = (const float*)&pm4[c];
            #pragma unroll
            for (int k = 0; k < 3; k++)
                #pragma unroll
                for (int e = 0; e < 4; e++)
                    acc[k][e] += pmc[e] * f[2*k + e];
        }

        #pragma unroll
        for (int k = 0; k < 3; k++) {
            int o = (i*3 + j)*3 + k;
            uint4 pk;
            pk.x = split_pack(acc[k][0] * (1.0f/27.0f));
            pk.y = split_pack(acc[k][1] * (1.0f/27.0f));
            pk.z = split_pack(acc[k][2] * (1.0f/27.0f));
            pk.w = split_pack(acc[k][3] * (1.0f/27.0f));
            *(uint4*)(g_sp_stack + (16 + o)*NS + vox) = pk;
        }
    }
}

// ---------------------------------------------------------------------------
// conv v9 = R14 compute path + TRIPLE-buffered staging (prefetch distance 2).
// NCOL=2 everywhere. wait_group 1 in steady state; wait_group 0 on last iter.
// ---------------------------------------------------------------------------
#define RSTRIDE 124
#define SROWS   64                    // 4 slots x 16 channels
#define SBUFW   (SROWS*RSTRIDE)       // 7936 words per buffer
#define SMEMB   (3*SBUFW*4)           // 95232 B dynamic (3 buffers)

template<int NCH, int NT, int CINR, int COUT, bool RELU, bool ADD, int OUT>
__global__ void __launch_bounds__(256, 2)
conv_mma5s(const uint32_t* __restrict__ in, const uint4* __restrict__ Bf,
           const float* __restrict__ bias, const float* __restrict__ addsrc,
           uint32_t* __restrict__ outp, float* __restrict__ outf)
{
    extern __shared__ __align__(16) uint32_t s_strip[];

    const int tid = threadIdx.x, wid = tid >> 5, lane = tid & 31;
    const int w0 = blockIdx.x*2, h = blockIdx.y;
    const int q = lane & 3, r = lane >> 2;
    const uint32_t sbase = smem_u32(s_strip);
    const int NSI = 3*NCH;

    float acc0[NT][4], acc1[NT][4];
    #pragma unroll
    for (int nt = 0; nt < NT; nt++)
        #pragma unroll
        for (int j = 0; j < 4; j++) { acc0[nt][j] = 0.0f; acc1[nt][j] = 0.0f; }

    // pre-zero pad words (tt in [0,4) and [116,124)) for all rows, 3 buffers
    for (int row = tid; row < 3*SROWS; row += 256) {
        uint32_t base = (row/SROWS)*SBUFW + (row % SROWS)*RSTRIDE;
        #pragma unroll
        for (int wZ = 0; wZ < 4; wZ++)    s_strip[base + wZ] = 0;
        #pragma unroll
        for (int wZ = 116; wZ < 124; wZ++) s_strip[base + wZ] = 0;
    }

    // stage (dh, chunk) = si : SROWS rows x 28 16B chunks
    auto stage = [&](int si, int buf) {
        const int dh = si / NCH, chunk = si % NCH;
        const int gh = h + dh - 1;
        const bool hok = ((unsigned)gh < HH);
        const int gwb = w0 - 1;
        const int rowbase = (gh*WW + gwb)*TTT;
        const uint32_t dbase = sbase + (uint32_t)buf*(SBUFW*4);
        for (int i = tid; i < SROWS*28; i += 256) {
            int row = i / 28;
            int j   = i - row*28;
            int slot = row >> 4, cil = row & 15;
            int ci = chunk*16 + cil;
            int gw = gwb + slot;
            bool ok = hok && ((unsigned)gw < WW) && (ci < CINR);
            int srcIdx = ok ? (ci*NS + rowbase + slot*TTT + j*4) : 0;
            cpasync16(dbase + (uint32_t)(row*RSTRIDE + 4 + j*4)*4, in + srcIdx, ok);
        }
        CP_COMMIT();
    };

    stage(0, 0);
    if (NSI > 1) stage(1, 1);

    int bsel = 0;
    for (int si = 0; si < NSI; si++) {
        if (si + 1 < NSI) CP_WAIT1(); else CP_WAIT0();
        __syncthreads();
        if (si + 2 < NSI) {
            int b2 = bsel + 2; if (b2 >= 3) b2 -= 3;
            stage(si + 2, b2);
        }

        const int dh = si / NCH, chunk = si % NCH;
        const uint32_t* S = s_strip + bsel*SBUFW;
        if (wid < 7) {
            const int m0 = wid*16 + r;
            #pragma unroll
            for (int dw = 0; dw < 3; dw++) {
                const int iterB = (dh*3 + dw)*NCH + chunk;
                const uint32_t* S0 = S + dw*(16*RSTRIDE);
                #pragma unroll
                for (int ks = 0; ks < 3; ks++) {
                    const int kb = ks*16 + q*2;
                    uint32_t aH0[4], aL0[4], aH1[4], aL1[4];
                    #pragma unroll
                    for (int half = 0; half < 2; half++) {
                        int k  = kb + half*8;
                        int c0 = (k*171) >> 9,  d0 = k - 3*c0;
                        int k1 = k + 1;
                        int c1 = (k1*171) >> 9, d1 = k1 - 3*c1;
                        int o00 = c0*RSTRIDE + m0 + d0 + 3;
                        int o01 = c1*RSTRIDE + m0 + d1 + 3;
                        uint32_t p00 = S0[o00];
                        uint32_t p01 = S0[o01];
                        uint32_t p10 = S0[o00 + 8];
                        uint32_t p11 = S0[o01 + 8];
                        aH0[half*2+0] = prmt(p00, p01, 0x7632);
                        aL0[half*2+0] = prmt(p00, p01, 0x5410);
                        aH0[half*2+1] = prmt(p10, p11, 0x7632);
                        aL0[half*2+1] = prmt(p10, p11, 0x5410);
                        uint32_t u00 = S0[16*RSTRIDE + o00];
                        uint32_t u01 = S0[16*RSTRIDE + o01];
                        uint32_t u10 = S0[16*RSTRIDE + o00 + 8];
                        uint32_t u11 = S0[16*RSTRIDE + o01 + 8];
                        aH1[half*2+0] = prmt(u00, u01, 0x7632);
                        aL1[half*2+0] = prmt(u00, u01, 0x5410);
                        aH1[half*2+1] = prmt(u10, u11, 0x7632);
                        aL1[half*2+1] = prmt(u10, u11, 0x5410);
                    }
                    const uint4* bp = Bf + (size_t)((iterB*3 + ks)*NT)*32 + lane;
                    #pragma unroll
                    for (int nt = 0; nt < NT; nt++) {
                        uint4 B = __ldg(bp + nt*32);
                        mma_bf16(acc0[nt], aH0, B.x, B.y);
                        mma_bf16(acc0[nt], aH0, B.z, B.w);
                        mma_bf16(acc0[nt], aL0, B.x, B.y);
                        mma_bf16(acc1[nt], aH1, B.x, B.y);
                        mma_bf16(acc1[nt], aH1, B.z, B.w);
                        mma_bf16(acc1[nt], aL1, B.x, B.y);
                    }
                }
            }
        }
        bsel++; if (bsel >= 3) bsel = 0;
    }

    if (wid < 7) {
        const int m0 = wid*16 + r;
        #pragma unroll
        for (int tile = 0; tile < 2; tile++) {
            const int vox = (h*WW + (w0 + tile))*TTT + m0;
            #pragma unroll
            for (int nt = 0; nt < NT; nt++) {
                #pragma unroll
                for (int j = 0; j < 2; j++) {
                    int n = nt*8 + 2*q + j;
                    if (n < COUT) {
                        float b = bias[n];
                        float v0 = (tile ? acc1[nt][j]   : acc0[nt][j])   + b;
                        float v1 = (tile ? acc1[nt][2+j] : acc0[nt][2+j]) + b;
                        if (RELU) { v0 = fmaxf(v0, 0.0f); v1 = fmaxf(v1, 0.0f); }
                        if (ADD)  { v0 += addsrc[n*NS + vox]; v1 += addsrc[n*NS + vox + 8]; }
                        if (OUT == 2) {
                            outf[n*NS + vox]     = v0;
                            outf[n*NS + vox + 8] = v1;
                        } else {
                            outp[n*NS + vox]     = split_pack(v0);
                            outp[n*NS + vox + 8] = split_pack(v1);
                            if (OUT == 1) {
                                outf[n*NS + vox]     = v0;
                                outf[n*NS + vox + 8] = v1;
                            }
                        }
                    }
                }
            }
        }
    }
}

// ---------------------------------------------------------------------------
extern "C" void kernel_launch(void* const* d_in, const int* in_sizes, int n_in,
                              void* d_out, int out_size)
{
    const float* x    = (const float*)d_in[0];
    const float* y    = (const float*)d_in[1];
    const float* flow = (const float*)d_in[2];
    const float* w1a  = (const float*)d_in[3];
    const float* b1a  = (const float*)d_in[4];
    const float* w1b  = (const float*)d_in[5];
    const float* b1b  = (const float*)d_in[6];
    const float* w2a  = (const float*)d_in[7];
    const float* b2a  = (const float*)d_in[8];
    const float* w2b  = (const float*)d_in[9];
    const float* b2b  = (const float*)d_in[10];
    const float* wf   = (const float*)d_in[11];
    const float* bf   = (const float*)d_in[12];
    float* out = (float*)d_out;

    void *p_spstack, *p_spt1, *p_h, *p_sph, *p_spt2, *p_sphr;
    void *p_Bf1a, *p_Bf1b, *p_Bf2a, *p_Bf2b, *p_Bff;
    cudaGetSymbolAddress(&p_spstack, g_sp_stack);
    cudaGetSymbolAddress(&p_spt1,    g_sp_t1);
    cudaGetSymbolAddress(&p_h,       g_h);
    cudaGetSymbolAddress(&p_sph,     g_sp_h);
    cudaGetSymbolAddress(&p_spt2,    g_sp_t2);
    cudaGetSymbolAddress(&p_sphr,    g_sp_hr);
    cudaGetSymbolAddress(&p_Bf1a,    g_Bf1a);
    cudaGetSymbolAddress(&p_Bf1b,    g_Bf1b);
    cudaGetSymbolAddress(&p_Bf2a,    g_Bf2a);
    cudaGetSymbolAddress(&p_Bf2b,    g_Bf2b);
    cudaGetSymbolAddress(&p_Bff,     g_Bff);

    cudaFuncSetAttribute(conv_mma5s<4,8,59,59,false,false,0>,
                         cudaFuncAttributeMaxDynamicSharedMemorySize, SMEMB);
    cudaFuncSetAttribute(conv_mma5s<4,2,59,16,true,false,1>,
                         cudaFuncAttributeMaxDynamicSharedMemorySize, SMEMB);
    cudaFuncSetAttribute(conv_mma5s<1,2,16,16,false,false,0>,
                         cudaFuncAttributeMaxDynamicSharedMemorySize, SMEMB);
    cudaFuncSetAttribute(conv_mma5s<1,2,16,16,true,true,0>,
                         cudaFuncAttributeMaxDynamicSharedMemorySize, SMEMB);
    cudaFuncSetAttribute(conv_mma5s<1,1,16,3,false,false,2>,
                         cudaFuncAttributeMaxDynamicSharedMemorySize, SMEMB);

    // 1: repack + warp (fused)
    prep_kernel<<<RPB + (NS + 255)/256, 256>>>(x, y, flow, w1a, w1b, w2a, w2b, wf);
    // 2: box sums (pm + pf fused)
    box_kernel<<<dim3(840 + 952, NC), 256>>>(y);
    // 3: correlation (4 voxels/thread, float4)
    corr_kernel<<<NS/4/256, 256>>>();

    dim3 mgrid(WW/2, HH);   // 48 x 80
    // 4: conv1a   [ncu profiles this]
    conv_mma5s<4,8,59,59,false,false,0><<<mgrid, 256, SMEMB>>>(
        (const uint32_t*)p_spstack, (const uint4*)p_Bf1a, b1a, nullptr,
        (uint32_t*)p_spt1, nullptr);
    // 5: conv1b + relu -> h f32 + packed
    conv_mma5s<4,2,59,16,true,false,1><<<mgrid, 256, SMEMB>>>(
        (const uint32_t*)p_spt1, (const uint4*)p_Bf1b, b1b, nullptr,
        (uint32_t*)p_sph, (float*)p_h);
    // 6: conv2a -> t2 packed
    conv_mma5s<1,2,16,16,false,false,0><<<mgrid, 256, SMEMB>>>(
        (const uint32_t*)p_sph, (const uint4*)p_Bf2a, b2a, nullptr,
        (uint32_t*)p_spt2, nullptr);
    // 7: conv2b: hr = h + relu(conv+b) -> packed
    conv_mma5s<1,2,16,16,true,true,0><<<mgrid, 256, SMEMB>>>(
        (const uint32_t*)p_spt2, (const uint4*)p_Bf2b, b2b, (const float*)p_h,
        (uint32_t*)p_sphr, nullptr);
    // 8: convf -> out f32
    conv_mma5s<1,1,16,3,false,false,2><<<mgrid, 256, SMEMB>>>(
        (const uint32_t*)p_sphr, (const uint4*)p_Bff, bf, nullptr,
        nullptr, out);
}

// round 17
// speedup vs baseline: 1.0645x; 1.0645x over previous
#include <cuda_runtime.h>
#include <cstdint>

#define HH 80
#define WW 96
#define TTT 112
#define NS (HH*WW*TTT)
#define NC 16
#define NCC 59
#define FH 40
#define FW 48
#define FT 56
#define PH 84
#define PW 100
#define PT 116
#define NSP (PH*PW*PT)

// ---------------------------------------------------------------------------
// scratch: packed activations = (bf16_hi << 16) | bf16_lo
// ---------------------------------------------------------------------------
__device__ uint32_t g_sp_stack[NCC*NS];
__device__ float    g_xw[NC*NS];
__device__ float    g_pm[NC*NS];
__device__ float    g_pf[NC*NSP];
__device__ uint32_t g_sp_t1[NCC*NS];
__device__ float    g_h[NC*NS];
__device__ uint32_t g_sp_h[NC*NS];
__device__ uint32_t g_sp_t2[NC*NS];
__device__ uint32_t g_sp_hr[NC*NS];

// B tables: [iter = tap*NCH+chunk][ks3][nt][lane32], uint4 = (b0h,b1h,b0l,b1l)
__device__ uint4 g_Bf1a[36*3*8*32];
__device__ uint4 g_Bf1b[36*3*2*32];
__device__ uint4 g_Bf2a[9*3*2*32];
__device__ uint4 g_Bf2b[9*3*2*32];
__device__ uint4 g_Bff [9*3*1*32];

// ---------------------------------------------------------------------------
// helpers
// ---------------------------------------------------------------------------
__device__ __forceinline__ uint32_t smem_u32(const void* p) {
    uint32_t a;
    asm("{ .reg .u64 t; cvta.to.shared.u64 t, %1; cvt.u32.u64 %0, t; }" : "=r"(a) : "l"(p));
    return a;
}
__device__ __forceinline__ uint32_t prmt(uint32_t a, uint32_t b, uint32_t s) {
    uint32_t d;
    asm("prmt.b32 %0, %1, %2, %3;" : "=r"(d) : "r"(a), "r"(b), "r"(s));
    return d;
}
__device__ __forceinline__ uint32_t split_pack(float v) {
    uint32_t u = __float_as_uint(v);
    uint32_t hb = u & 0xffff0000u;
    float r = v - __uint_as_float(hb);
    uint16_t lo;
    asm("cvt.rn.bf16.f32 %0, %1;" : "=h"(lo) : "f"(r));
    return hb | (uint32_t)lo;
}
__device__ __forceinline__ void split_pair(float v0, float v1, uint32_t& hi, uint32_t& lo) {
    uint32_t u0 = __float_as_uint(v0), u1 = __float_as_uint(v1);
    hi = prmt(u0, u1, 0x7632);
    float h0 = __uint_as_float(u0 & 0xffff0000u);
    float h1 = __uint_as_float(u1 & 0xffff0000u);
    float l0 = v0 - h0, l1 = v1 - h1;
    asm("cvt.rn.satfinite.bf16x2.f32 %0, %1, %2;" : "=r"(lo) : "f"(l1), "f"(l0));
}
__device__ __forceinline__ void mma_bf16(float* c, const uint32_t* a, uint32_t b0, uint32_t b1) {
    asm volatile("mma.sync.aligned.m16n8k16.row.col.f32.bf16.bf16.f32 "
        "{%0,%1,%2,%3}, {%4,%5,%6,%7}, {%8,%9}, {%0,%1,%2,%3};"
        : "+f"(c[0]), "+f"(c[1]), "+f"(c[2]), "+f"(c[3])
        : "r"(a[0]), "r"(a[1]), "r"(a[2]), "r"(a[3]), "r"(b0), "r"(b1));
}
// 16B cp.async, L1-allocating (.ca — R11 proved .cg's L1 bypass regresses)
__device__ __forceinline__ void cpasync16(uint32_t dst, const void* src, bool ok) {
    int sz = ok ? 16 : 0;
    asm volatile("cp.async.ca.shared.global [%0], [%1], 16, %2;"
                 :: "r"(dst), "l"(src), "r"(sz) : "memory");
}
#define CP_COMMIT() asm volatile("cp.async.commit_group;" ::: "memory")
#define CP_WAIT0()  asm volatile("cp.async.wait_group 0;" ::: "memory")

// ---------------------------------------------------------------------------
// repack (R5-proven layout)
// ---------------------------------------------------------------------------
__device__ void repack_one(int idx, const float* __restrict__ w, uint4* __restrict__ dst,
                           int NT, int NCH, int CIN, int COUT)
{
    int lane = idx & 31;
    int rest = idx >> 5;
    int nt = rest % NT;   rest /= NT;
    int ks = rest % 3;    rest /= 3;
    int iter = rest;
    int tap = iter / NCH, chunk = iter % NCH;
    int n = nt*8 + (lane >> 2);
    int q = lane & 3;
    int dh = tap/3, dw = tap%3;
    float v[4];
    #pragma unroll
    for (int j = 0; j < 4; j++) {
        int k = ks*16 + q*2 + (j >> 1)*8 + (j & 1);
        int cil = k/3, dt = k - 3*cil;
        int ci = chunk*16 + cil;
        v[j] = (ci < CIN && n < COUT) ? w[(n*CIN + ci)*27 + dh*9 + dw*3 + dt] : 0.0f;
    }
    uint32_t h0, l0, h1, l1;
    split_pair(v[0], v[1], h0, l0);
    split_pair(v[2], v[3], h1, l1);
    dst[idx] = make_uint4(h0, h1, l0, l1);
}

// ---------------------------------------------------------------------------
// prep = repack + warp/upsample (R9-proven)
// ---------------------------------------------------------------------------
#define RPB 152
__global__ void prep_kernel(const float* __restrict__ x, const float* __restrict__ y,
                            const float* __restrict__ flow,
                            const float* __restrict__ w1a, const float* __restrict__ w1b,
                            const float* __restrict__ w2a, const float* __restrict__ w2b,
                            const float* __restrict__ wf)
{
    if (blockIdx.x < RPB) {
        int gi = blockIdx.x*256 + threadIdx.x;
        if      (gi < 27648)  repack_one(gi,        w1a, g_Bf1a, 8, 4, 59, 59);
        else if (gi < 34560)  repack_one(gi-27648,  w1b, g_Bf1b, 2, 4, 59, 16);
        else if (gi < 36288)  repack_one(gi-34560,  w2a, g_Bf2a, 2, 1, 16, 16);
        else if (gi < 38016)  repack_one(gi-36288,  w2b, g_Bf2b, 2, 1, 16, 16);
        else if (gi < 38880)  repack_one(gi-38016,  wf,  g_Bff,  1, 1, 16, 3);
        return;
    }
    int idx = (blockIdx.x - RPB)*256 + threadIdx.x;
    if (idx >= NS) return;
    int t = idx % TTT, w = (idx / TTT) % WW, h = idx / (TTT*WW);

    float ph = h * (39.0f/79.0f), pw = w * (47.0f/95.0f), pt = t * (55.0f/111.0f);
    int ih = (int)ph; if (ih > FH-2) ih = FH-2;
    int iw = (int)pw; if (iw > FW-2) iw = FW-2;
    int it = (int)pt; if (it > FT-2) it = FT-2;
    float fh = ph - (float)ih, fw = pw - (float)iw, ft = pt - (float)it;

    float fu[3];
    #pragma unroll
    for (int c = 0; c < 3; c++) {
        const float* fc = flow + c*(FH*FW*FT) + (ih*FW + iw)*FT + it;
        float v000 = fc[0],        v001 = fc[1];
        float v010 = fc[FT],       v011 = fc[FT+1];
        float v100 = fc[FW*FT],    v101 = fc[FW*FT+1];
        float v110 = fc[FW*FT+FT], v111 = fc[FW*FT+FT+1];
        float a0 = v000*(1.0f-ft) + v001*ft;
        float a1 = v010*(1.0f-ft) + v011*ft;
        float a2 = v100*(1.0f-ft) + v101*ft;
        float a3 = v110*(1.0f-ft) + v111*ft;
        float b0 = a0*(1.0f-fw) + a1*fw;
        float b1 = a2*(1.0f-fw) + a3*fw;
        fu[c] = 2.0f*(b0*(1.0f-fh) + b1*fh);
    }

    float cx = (float)h + fu[0], cy = (float)w + fu[1], cz = (float)t + fu[2];
    float x0f = floorf(cx), y0f = floorf(cy), z0f = floorf(cz);
    float fx = cx - x0f, fy = cy - y0f, fz = cz - z0f;
    int x0 = (int)x0f, y0 = (int)y0f, z0 = (int)z0f;

    float acc[NC];
    #pragma unroll
    for (int c = 0; c < NC; c++) acc[c] = 0.0f;
    #pragma unroll
    for (int dx = 0; dx < 2; dx++)
    #pragma unroll
    for (int dy = 0; dy < 2; dy++)
    #pragma unroll
    for (int dz = 0; dz < 2; dz++) {
        int ix = x0+dx, iy = y0+dy, iz = z0+dz;
        if (ix < 0 || ix >= HH || iy < 0 || iy >= WW || iz < 0 || iz >= TTT) continue;
        float wgt = (dx ? fx : 1.0f-fx) * (dy ? fy : 1.0f-fy) * (dz ? fz : 1.0f-fz);
        const float* xp = x + (ix*WW + iy)*TTT + iz;
        #pragma unroll
        for (int c = 0; c < NC; c++) acc[c] += wgt * xp[c*NS];
    }
    #pragma unroll
    for (int c = 0; c < NC; c++) {
        g_xw[c*NS + idx] = acc[c];
        g_sp_stack[c*NS + idx]      = split_pack(acc[c]);
        g_sp_stack[(43+c)*NS + idx] = split_pack(y[c*NS + idx]);
    }
}

// ---------------------------------------------------------------------------
// box v2: float4 loads. Out-of-range chunks contribute exact 0.0 adds ->
// bit-identical to R15 (per-row accumulation order unchanged).
// ---------------------------------------------------------------------------
__global__ void box_kernel(const float* __restrict__ y)
{
    int c = blockIdx.y;
    if (blockIdx.x < 840) {
        int id = blockIdx.x*256 + threadIdx.x;          // NS/4 threads
        int t4 = (id % 28)*4;                           // 0..108
        int w  = (id / 28) % WW;
        int h  = id / (28*WW);
        float R[6];
        #pragma unroll
        for (int e = 0; e < 6; e++) R[e] = 0.0f;
        const bool okA = (t4 >= 4);
        const bool okC = (t4 <= 104);                   // t4+4 <= 108
        #pragma unroll
        for (int dh = -1; dh <= 1; dh++) {
            int gh = h + dh; if ((unsigned)gh >= HH) continue;
            #pragma unroll
            for (int dw = -1; dw <= 1; dw++) {
                int gw = w + dw; if ((unsigned)gw >= WW) continue;
                const float* row = g_xw + c*NS + (gh*WW + gw)*TTT;
                float4 fB = *(const float4*)(row + t4);
                float4 fA = okA ? *(const float4*)(row + t4 - 4) : make_float4(0,0,0,0);
                float4 fC = okC ? *(const float4*)(row + t4 + 4) : make_float4(0,0,0,0);
                R[0] += fA.w;
                R[1] += fB.x; R[2] += fB.y; R[3] += fB.z; R[4] += fB.w;
                R[5] += fC.x;
            }
        }
        float* o = g_pm + c*NS + (h*WW + w)*TTT + t4;
        #pragma unroll
        for (int i = 0; i < 4; i++) o[i] = R[i] + R[i+1] + R[i+2];
    } else {
        int id = (blockIdx.x - 840)*256 + threadIdx.x;
        if (id >= 243600) return;                        // PH*PW*(PT/4)
        int t4 = (id % 29)*4;                            // 0..112
        int b  = (id / 29) % PW;
        int a  = id / (29*PW);
        int hc = a - 2, wc = b - 2;
        float R[6];
        #pragma unroll
        for (int e = 0; e < 6; e++) R[e] = 0.0f;
        const bool okA = (t4 >= 4);
        const bool okB = (t4 <= 108);
        #pragma unroll
        for (int dh = -1; dh <= 1; dh++) {
            int gh = hc + dh; if ((unsigned)gh >= HH) continue;
            #pragma unroll
            for (int dw = -1; dw <= 1; dw++) {
                int gw = wc + dw; if ((unsigned)gw >= WW) continue;
                const float* row = y + c*NS + (gh*WW + gw)*TTT;
                float4 fA = okA ? *(const float4*)(row + t4 - 4) : make_float4(0,0,0,0);
                float4 fB = okB ? *(const float4*)(row + t4)     : make_float4(0,0,0,0);
                // window gt = t4-3 .. t4+2
                R[0] += fA.y; R[1] += fA.z; R[2] += fA.w;
                R[3] += fB.x; R[4] += fB.y; R[5] += fB.z;
            }
        }
        float* o = g_pf + c*NSP + (a*PW + b)*PT + t4;
        #pragma unroll
        for (int i = 0; i < 4; i++) o[i] = R[i] + R[i+1] + R[i+2];
    }
}

// ---------------------------------------------------------------------------
// corr (R13: 4 voxels/thread, float4; bit-identical results)
// ---------------------------------------------------------------------------
__global__ void __launch_bounds__(256)
corr_kernel()
{
    int id = blockIdx.x*256 + threadIdx.x;              // NS/4 = 215040 exact
    int t4 = (id % 28)*4;
    int w  = (id / 28) % WW;
    int h  = id / (28*WW);
    int vox = (h*WW + w)*TTT + t4;

    float4 pm4[NC];
    #pragma unroll
    for (int c = 0; c < NC; c++)
        pm4[c] = *(const float4*)(g_pm + c*NS + vox);

    #pragma unroll
    for (int i = 0; i < 3; i++)
    #pragma unroll
    for (int j = 0; j < 3; j++) {
        const float* rowbase = g_pf + ((h + 2*i)*PW + (w + 2*j))*PT + t4;
        float acc[3][4];
        #pragma unroll
        for (int k = 0; k < 3; k++)
            #pragma unroll
            for (int e = 0; e < 4; e++) acc[k][e] = 0.0f;

        #pragma unroll
        for (int c = 0; c < NC; c++) {
            float4 f0 = *(const float4*)(rowbase + c*NSP);
            float4 f1 = *(const float4*)(rowbase + c*NSP + 4);
            float f[8] = {f0.x, f0.y, f0.z, f0.w, f1.x, f1.y, f1.z, f1.w};
            const float* pmc = (const float*)&pm4[c];
            #pragma unroll
            for (int k = 0; k < 3; k++)
                #pragma unroll
                for (int e = 0; e < 4; e++)
                    acc[k][e] += pmc[e] * f[2*k + e];
        }

        #pragma unroll
        for (int k = 0; k < 3; k++) {
            int o = (i*3 + j)*3 + k;
            uint4 pk;
            pk.x = split_pack(acc[k][0] * (1.0f/27.0f));
            pk.y = split_pack(acc[k][1] * (1.0f/27.0f));
            pk.z = split_pack(acc[k][2] * (1.0f/27.0f));
            pk.w = split_pack(acc[k][3] * (1.0f/27.0f));
            *(uint4*)(g_sp_stack + (16 + o)*NS + vox) = pk;
        }
    }
}

// ---------------------------------------------------------------------------
// conv (R15-proven): NCOL columns/CTA, stage NCOL+2 slots per (dh,chunk),
// double-buffered .ca cp.async. NCOL=2 for conv1a, NCOL=4 for small layers.
// ---------------------------------------------------------------------------
#define RSTRIDE 124

template<int NCOL, int NCH, int NT, int CINR, int COUT, bool RELU, bool ADD, int OUT>
__global__ void __launch_bounds__(256, 2)
conv_mma4s(const uint32_t* __restrict__ in, const uint4* __restrict__ Bf,
           const float* __restrict__ bias, const float* __restrict__ addsrc,
           uint32_t* __restrict__ outp, float* __restrict__ outf)
{
    constexpr int SLOTS = NCOL + 2;
    constexpr int SROWS = SLOTS * 16;
    constexpr int SBUFW = SROWS * RSTRIDE;
    extern __shared__ __align__(16) uint32_t s_strip[];

    const int tid = threadIdx.x, wid = tid >> 5, lane = tid & 31;
    const int w0 = blockIdx.x*NCOL, h = blockIdx.y;
    const int q = lane & 3, r = lane >> 2;
    const uint32_t sbase = smem_u32(s_strip);
    const int NSI = 3*NCH;

    float acc[NCOL][NT][4];
    #pragma unroll
    for (int cidx = 0; cidx < NCOL; cidx++)
        #pragma unroll
        for (int nt = 0; nt < NT; nt++)
            #pragma unroll
            for (int j = 0; j < 4; j++) acc[cidx][nt][j] = 0.0f;

    // pre-zero pad words (tt in [0,4) and [116,124)) for all rows, both buffers
    for (int row = tid; row < 2*SROWS; row += 256) {
        uint32_t base = (row >= SROWS ? SBUFW : 0) + (row % SROWS)*RSTRIDE;
        #pragma unroll
        for (int wZ = 0; wZ < 4; wZ++)    s_strip[base + wZ] = 0;
        #pragma unroll
        for (int wZ = 116; wZ < 124; wZ++) s_strip[base + wZ] = 0;
    }

    // stage (dh, chunk) = si : SROWS rows x 28 16B chunks
    auto stage = [&](int si, int buf) {
        const int dh = si / NCH, chunk = si % NCH;
        const int gh = h + dh - 1;
        const bool hok = ((unsigned)gh < HH);
        const int gwb = w0 - 1;
        const int rowbase = (gh*WW + gwb)*TTT;
        const uint32_t dbase = sbase + (uint32_t)buf*(SBUFW*4);
        for (int i = tid; i < SROWS*28; i += 256) {
            int row = i / 28;
            int j   = i - row*28;
            int slot = row >> 4, cil = row & 15;
            int ci = chunk*16 + cil;
            int gw = gwb + slot;
            bool ok = hok && ((unsigned)gw < WW) && (ci < CINR);
            int srcIdx = ok ? (ci*NS + rowbase + slot*TTT + j*4) : 0;
            cpasync16(dbase + (uint32_t)(row*RSTRIDE + 4 + j*4)*4, in + srcIdx, ok);
        }
        CP_COMMIT();
    };

    stage(0, 0);
    int cur = 0;

    for (int si = 0; si < NSI; si++) {
        CP_WAIT0();
        __syncthreads();
        if (si + 1 < NSI) stage(si + 1, cur ^ 1);

        const int dh = si / NCH, chunk = si % NCH;
        const uint32_t* S = s_strip + cur*SBUFW;
        if (wid < 7) {
            const int m0 = wid*16 + r;
            #pragma unroll
            for (int dw = 0; dw < 3; dw++) {
                const int iterB = (dh*3 + dw)*NCH + chunk;
                const uint32_t* S0 = S + dw*(16*RSTRIDE);
                #pragma unroll
                for (int ks = 0; ks < 3; ks++) {
                    const int kb = ks*16 + q*2;
                    uint32_t aH[NCOL][4], aL[NCOL][4];
                    #pragma unroll
                    for (int half = 0; half < 2; half++) {
                        int k  = kb + half*8;
                        int c0 = (k*171) >> 9,  d0 = k - 3*c0;
                        int k1 = k + 1;
                        int c1 = (k1*171) >> 9, d1 = k1 - 3*c1;
                        int o00 = c0*RSTRIDE + m0 + d0 + 3;
                        int o01 = c1*RSTRIDE + m0 + d1 + 3;
                        #pragma unroll
                        for (int cidx = 0; cidx < NCOL; cidx++) {
                            const uint32_t* Sc = S0 + cidx*(16*RSTRIDE);
                            uint32_t p00 = Sc[o00];
                            uint32_t p01 = Sc[o01];
                            uint32_t p10 = Sc[o00 + 8];
                            uint32_t p11 = Sc[o01 + 8];
                            aH[cidx][half*2+0] = prmt(p00, p01, 0x7632);
                            aL[cidx][half*2+0] = prmt(p00, p01, 0x5410);
                            aH[cidx][half*2+1] = prmt(p10, p11, 0x7632);
                            aL[cidx][half*2+1] = prmt(p10, p11, 0x5410);
                        }
                    }
                    const uint4* bp = Bf + (size_t)((iterB*3 + ks)*NT)*32 + lane;
                    #pragma unroll
                    for (int nt = 0; nt < NT; nt++) {
                        uint4 B = __ldg(bp + nt*32);
                        #pragma unroll
                        for (int cidx = 0; cidx < NCOL; cidx++) {
                            mma_bf16(acc[cidx][nt], aH[cidx], B.x, B.y);
                            mma_bf16(acc[cidx][nt], aH[cidx], B.z, B.w);
                            mma_bf16(acc[cidx][nt], aL[cidx], B.x, B.y);
                        }
                    }
                }
            }
        }
        cur ^= 1;
    }

    if (wid < 7) {
        const int m0 = wid*16 + r;
        #pragma unroll
        for (int tile = 0; tile < NCOL; tile++) {
            const int vox = (h*WW + (w0 + tile))*TTT + m0;
            #pragma unroll
            for (int nt = 0; nt < NT; nt++) {
                #pragma unroll
                for (int j = 0; j < 2; j++) {
                    int n = nt*8 + 2*q + j;
                    if (n < COUT) {
                        float b = bias[n];
                        float v0 = acc[tile][nt][j]   + b;
                        float v1 = acc[tile][nt][2+j] + b;
                        if (RELU) { v0 = fmaxf(v0, 0.0f); v1 = fmaxf(v1, 0.0f); }
                        if (ADD)  { v0 += addsrc[n*NS + vox]; v1 += addsrc[n*NS + vox + 8]; }
                        if (OUT == 2) {
                            outf[n*NS + vox]     = v0;
                            outf[n*NS + vox + 8] = v1;
                        } else {
                            outp[n*NS + vox]     = split_pack(v0);
                            outp[n*NS + vox + 8] = split_pack(v1);
                            if (OUT == 1) {
                                outf[n*NS + vox]     = v0;
                                outf[n*NS + vox + 8] = v1;
                            }
                        }
                    }
                }
            }
        }
    }
}

// ---------------------------------------------------------------------------
extern "C" void kernel_launch(void* const* d_in, const int* in_sizes, int n_in,
                              void* d_out, int out_size)
{
    const float* x    = (const float*)d_in[0];
    const float* y    = (const float*)d_in[1];
    const float* flow = (const float*)d_in[2];
    const float* w1a  = (const float*)d_in[3];
    const float* b1a  = (const float*)d_in[4];
    const float* w1b  = (const float*)d_in[5];
    const float* b1b  = (const float*)d_in[6];
    const float* w2a  = (const float*)d_in[7];
    const float* b2a  = (const float*)d_in[8];
    const float* w2b  = (const float*)d_in[9];
    const float* b2b  = (const float*)d_in[10];
    const float* wf   = (const float*)d_in[11];
    const float* bf   = (const float*)d_in[12];
    float* out = (float*)d_out;

    void *p_spstack, *p_spt1, *p_h, *p_sph, *p_spt2, *p_sphr;
    void *p_Bf1a, *p_Bf1b, *p_Bf2a, *p_Bf2b, *p_Bff;
    cudaGetSymbolAddress(&p_spstack, g_sp_stack);
    cudaGetSymbolAddress(&p_spt1,    g_sp_t1);
    cudaGetSymbolAddress(&p_h,       g_h);
    cudaGetSymbolAddress(&p_sph,     g_sp_h);
    cudaGetSymbolAddress(&p_spt2,    g_sp_t2);
    cudaGetSymbolAddress(&p_sphr,    g_sp_hr);
    cudaGetSymbolAddress(&p_Bf1a,    g_Bf1a);
    cudaGetSymbolAddress(&p_Bf1b,    g_Bf1b);
    cudaGetSymbolAddress(&p_Bf2a,    g_Bf2a);
    cudaGetSymbolAddress(&p_Bf2b,    g_Bf2b);
    cudaGetSymbolAddress(&p_Bff,     g_Bff);

    constexpr int SM2 = 2*4*16*RSTRIDE*4;   // NCOL=2: 63488 B
    constexpr int SM4 = 2*6*16*RSTRIDE*4;   // NCOL=4: 95232 B
    cudaFuncSetAttribute(conv_mma4s<2,4,8,59,59,false,false,0>,
                         cudaFuncAttributeMaxDynamicSharedMemorySize, SM2);
    cudaFuncSetAttribute(conv_mma4s<4,4,2,59,16,true,false,1>,
                         cudaFuncAttributeMaxDynamicSharedMemorySize, SM4);
    cudaFuncSetAttribute(conv_mma4s<4,1,2,16,16,false,false,0>,
                         cudaFuncAttributeMaxDynamicSharedMemorySize, SM4);
    cudaFuncSetAttribute(conv_mma4s<4,1,2,16,16,true,true,0>,
                         cudaFuncAttributeMaxDynamicSharedMemorySize, SM4);
    cudaFuncSetAttribute(conv_mma4s<4,1,1,16,3,false,false,2>,
                         cudaFuncAttributeMaxDynamicSharedMemorySize, SM4);

    // 1: repack + warp (fused)
    prep_kernel<<<RPB + (NS + 255)/256, 256>>>(x, y, flow, w1a, w1b, w2a, w2b, wf);
    // 2: box sums (pm + pf fused, float4)
    box_kernel<<<dim3(840 + 952, NC), 256>>>(y);
    // 3: correlation (4 voxels/thread, float4)
    corr_kernel<<<NS/4/256, 256>>>();

    dim3 mgrid2(WW/2, HH);   // 48 x 80
    dim3 mgrid4(WW/4, HH);   // 24 x 80
    // 4: conv1a (NCOL=2, NT=8)   [ncu profiles this]
    conv_mma4s<2,4,8,59,59,false,false,0><<<mgrid2, 256, SM2>>>(
        (const uint32_t*)p_spstack, (const uint4*)p_Bf1a, b1a, nullptr,
        (uint32_t*)p_spt1, nullptr);
    // 5: conv1b (NCOL=4) + relu -> h f32 + packed
    conv_mma4s<4,4,2,59,16,true,false,1><<<mgrid4, 256, SM4>>>(
        (const uint32_t*)p_spt1, (const uint4*)p_Bf1b, b1b, nullptr,
        (uint32_t*)p_sph, (float*)p_h);
    // 6: conv2a (NCOL=4) -> t2 packed
    conv_mma4s<4,1,2,16,16,false,false,0><<<mgrid4, 256, SM4>>>(
        (const uint32_t*)p_sph, (const uint4*)p_Bf2a, b2a, nullptr,
        (uint32_t*)p_spt2, nullptr);
    // 7: conv2b (NCOL=4): hr = h + relu(conv+b) -> packed
    conv_mma4s<4,1,2,16,16,true,true,0><<<mgrid4, 256, SM4>>>(
        (const uint32_t*)p_spt2, (const uint4*)p_Bf2b, b2b, (const float*)p_h,
        (uint32_t*)p_sphr, nullptr);
    // 8: convf (NCOL=4) -> out f32
    conv_mma4s<4,1,1,16,3,false,false,2><<<mgrid4, 256, SM4>>>(
        (const uint32_t*)p_sphr, (const uint4*)p_Bff, bf, nullptr,
        nullptr, out);
}